// round 15
// baseline (speedup 1.0000x reference)
#include <cuda_runtime.h>
#include <cuda_fp16.h>
#include <mma.h>
#include <math.h>
#include <cstdint>

using namespace nvcuda;

// Constants
#define Ll 12
#define Dd 768
#define Bb 4
#define Tt 256
#define Ff 3072
#define MM (Bb*Tt)   // 1024
#define MD (MM*Dd)

// fp16 weight offsets (elements), NATIVE [K,N] layout per layer slice
#define NDD (Ll*Dd*Dd)
#define NDF (Ll*Dd*Ff)
#define OFF_WK 0
#define OFF_WV (NDD)
#define OFF_WR (2*NDD)
#define OFF_WO (3*NDD)
#define OFF_FK (4*NDD)
#define OFF_FV (4*NDD + NDF)
#define OFF_FR (4*NDD + 2*NDF)
#define NWTOT  (4*NDD + 2*NDF + NDD)

// ---------------- scratch (device globals) ----------
__device__ __align__(256) float g_x[MD];        // residual ping
__device__ __align__(256) float g_x2[MD];       // residual pong
__device__ __align__(256) float g_kvr[3*MD];    // k, v, sigmoid(r)
__device__ __align__(256) float g_r2[MD];
__device__ __align__(256) float g_part[3*MD];
__device__ __align__(256) __half g_mixh[3*MD];  // mixed activations (fp16)
__device__ __align__(256) __half g_rwkvh[MD];
__device__ __align__(256) __half g_hh[MM*Ff];
__device__ __align__(256) __half g_w[NWTOT];    // W fp16 [K,N] native

// ---------------- cp.async helpers ----------------
__device__ __forceinline__ void cpa16(void* dst, const void* src) {
    unsigned d = (unsigned)__cvta_generic_to_shared(dst);
    asm volatile("cp.async.cg.shared.global [%0], [%1], 16;" :: "r"(d), "l"(src));
}
__device__ __forceinline__ void cp_commit() { asm volatile("cp.async.commit_group;"); }
template<int N> __device__ __forceinline__ void cp_wait() {
    asm volatile("cp.async.wait_group %0;" :: "n"(N));
}

// ---------------- fused streaming convert: all 7 weights, one launch -------
struct ConvArgs {
    const float4* src[7];
    uint4* dst[7];
    int n8[7];
    int cum[8];
};
__global__ void convAll_kernel(ConvArgs ca) {
    int blk = blockIdx.x;
    int y = 0;
    #pragma unroll
    for (int t = 1; t < 7; t++)
        if (blk >= ca.cum[t]) y = t;
    int local = blk - ca.cum[y];
    const float4* W = ca.src[y];
    uint4* out = ca.dst[y];
    int n8 = ca.n8[y];
    int i = local * 1024 + threadIdx.x;
    #pragma unroll
    for (int u = 0; u < 4; u++, i += 256) {
        if (i < n8) {
            float4 a = W[2*i], b = W[2*i+1];
            __half2 h0 = __floats2half2_rn(a.x, a.y);
            __half2 h1 = __floats2half2_rn(a.z, a.w);
            __half2 h2 = __floats2half2_rn(b.x, b.y);
            __half2 h3 = __floats2half2_rn(b.z, b.w);
            uint4 o;
            o.x = *(unsigned*)&h0; o.y = *(unsigned*)&h1;
            o.z = *(unsigned*)&h2; o.w = *(unsigned*)&h3;
            out[i] = o;
        }
    }
}

// ---------------- block reduces ----------------
__device__ __forceinline__ float blockReduceSum(float v, float* sh) {
    int lane = threadIdx.x & 31, w = threadIdx.x >> 5;
    #pragma unroll
    for (int o = 16; o; o >>= 1) v += __shfl_xor_sync(0xffffffffu, v, o);
    if (lane == 0) sh[w] = v;
    __syncthreads();
    float r;
    if (threadIdx.x < 8) {
        r = sh[threadIdx.x];
        #pragma unroll
        for (int o = 4; o; o >>= 1) r += __shfl_xor_sync(0x000000ffu, r, o);
        if (threadIdx.x == 0) sh[0] = r;
    }
    __syncthreads();
    r = sh[0];
    __syncthreads();
    return r;
}
__device__ __forceinline__ float3 blockReduceSum3(float3 v, float3* sh) {
    int lane = threadIdx.x & 31, w = threadIdx.x >> 5;
    #pragma unroll
    for (int o = 16; o; o >>= 1) {
        v.x += __shfl_xor_sync(0xffffffffu, v.x, o);
        v.y += __shfl_xor_sync(0xffffffffu, v.y, o);
        v.z += __shfl_xor_sync(0xffffffffu, v.z, o);
    }
    if (lane == 0) sh[w] = v;
    __syncthreads();
    float3 r;
    if (threadIdx.x < 8) {
        r = sh[threadIdx.x];
        #pragma unroll
        for (int o = 4; o; o >>= 1) {
            r.x += __shfl_xor_sync(0x000000ffu, r.x, o);
            r.y += __shfl_xor_sync(0x000000ffu, r.y, o);
            r.z += __shfl_xor_sync(0x000000ffu, r.z, o);
        }
        if (threadIdx.x == 0) sh[0] = r;
    }
    __syncthreads();
    r = sh[0];
    __syncthreads();
    return r;
}

// ---------------- embedding gather + LN (ln0) ----------------
__global__ void embed_ln_kernel(const int* __restrict__ tokens,
                                const float* __restrict__ emb,
                                const float* __restrict__ w,
                                const float* __restrict__ b,
                                float* __restrict__ Y) {
    __shared__ float sh[8];
    int m = blockIdx.x;
    int tok = tokens[m];
    const float* xr = emb + (size_t)tok * Dd;
    int i0 = threadIdx.x, i1 = i0 + 256, i2 = i0 + 512;
    float v0 = xr[i0], v1 = xr[i1], v2 = xr[i2];
    float s = blockReduceSum(v0 + v1 + v2, sh);
    float mu = s * (1.0f / 768.0f);
    float c0 = v0 - mu, c1 = v1 - mu, c2 = v2 - mu;
    float ss = blockReduceSum(c0*c0 + c1*c1 + c2*c2, sh);
    float inv = rsqrtf(ss * (1.0f / 768.0f) + 1e-5f);
    float* yr = Y + (size_t)m * Dd;
    yr[i0] = c0 * inv * w[i0] + b[i0];
    yr[i1] = c1 * inv * w[i1] + b[i1];
    yr[i2] = c2 * inv * w[i2] + b[i2];
}

// ---------------- final LN with fused gated split-K reduction --------------
__global__ void ln_red_kernel(const float* __restrict__ X,
                              const float* __restrict__ g,
                              const float* __restrict__ q0,
                              const float* __restrict__ q1,
                              const float* __restrict__ q2,
                              const float* __restrict__ w,
                              const float* __restrict__ b,
                              float* __restrict__ Y) {
    __shared__ float sh[8];
    int m = blockIdx.x;
    size_t base = (size_t)m * Dd;
    int i0 = threadIdx.x, i1 = i0 + 256, i2 = i0 + 512;
    float v0 = X[base+i0] + g[base+i0] * (q0[base+i0] + q1[base+i0] + q2[base+i0]);
    float v1 = X[base+i1] + g[base+i1] * (q0[base+i1] + q1[base+i1] + q2[base+i1]);
    float v2 = X[base+i2] + g[base+i2] * (q0[base+i2] + q1[base+i2] + q2[base+i2]);
    float s = blockReduceSum(v0 + v1 + v2, sh);
    float mu = s * (1.0f / 768.0f);
    float c0 = v0 - mu, c1 = v1 - mu, c2 = v2 - mu;
    float ss = blockReduceSum(c0*c0 + c1*c1 + c2*c2, sh);
    float inv = rsqrtf(ss * (1.0f / 768.0f) + 1e-5f);
    float* yr = Y + base;
    yr[i0] = c0 * inv * w[i0] + b[i0];
    yr[i1] = c1 * inv * w[i1] + b[i1];
    yr[i2] = c2 * inv * w[i2] + b[i2];
}

// ------- fused [split-K reduce +] LN + token-shift mix, 2 rows/block -------
// RED: 0 = none; 1 = x += q0+q1+q2; 2 = x += gate*(q0+q1+q2)
// Block handles rows r0=2*blk, r1=r0+1. Computes 3 LNs (prev, r0, r1);
// r1's token-shift source is r0's LN (already computed).
template<int NMIX, int RED>
__global__ void lnmix_kernel(const float* __restrict__ X,
                             const float* __restrict__ gate,
                             const float* __restrict__ q0,
                             const float* __restrict__ q1,
                             const float* __restrict__ q2,
                             float* __restrict__ Xout,
                             const float* __restrict__ w,
                             const float* __restrict__ b,
                             const float* __restrict__ mk,
                             const float* __restrict__ mv,
                             const float* __restrict__ mr,
                             __half* __restrict__ oh) {
    __shared__ float3 sh[8];
    int r0 = blockIdx.x * 2;
    bool hasPrev = (r0 & (Tt - 1)) != 0;
    size_t b0 = (size_t)r0 * Dd;
    size_t b1 = b0 + Dd;
    size_t bp = b0 - Dd;

    float c0[3], c1[3], pv[3];
    #pragma unroll
    for (int q = 0; q < 3; q++) {
        int i = threadIdx.x + q * 256;
        float v0 = X[b0 + i];
        float v1 = X[b1 + i];
        if (RED == 1) {
            v0 += q0[b0+i] + q1[b0+i] + q2[b0+i];
            v1 += q0[b1+i] + q1[b1+i] + q2[b1+i];
        } else if (RED == 2) {
            v0 += gate[b0+i] * (q0[b0+i] + q1[b0+i] + q2[b0+i]);
            v1 += gate[b1+i] * (q0[b1+i] + q1[b1+i] + q2[b1+i]);
        }
        if (RED) { Xout[b0 + i] = v0; Xout[b1 + i] = v1; }
        c0[q] = v0; c1[q] = v1;
        float p = 0.0f;
        if (hasPrev) {
            p = X[bp + i];
            if (RED == 1) p += q0[bp+i] + q1[bp+i] + q2[bp+i];
            else if (RED == 2) p += gate[bp+i] * (q0[bp+i] + q1[bp+i] + q2[bp+i]);
        }
        pv[q] = p;
    }

    float3 s = blockReduceSum3(make_float3(c0[0]+c0[1]+c0[2],
                                           c1[0]+c1[1]+c1[2],
                                           pv[0]+pv[1]+pv[2]), sh);
    float mu0 = s.x * (1.0f / 768.0f);
    float mu1 = s.y * (1.0f / 768.0f);
    float mup = s.z * (1.0f / 768.0f);
    float d0[3], d1[3], dp[3];
    #pragma unroll
    for (int q = 0; q < 3; q++) { d0[q] = c0[q] - mu0; d1[q] = c1[q] - mu1; dp[q] = pv[q] - mup; }
    float3 ss = blockReduceSum3(make_float3(d0[0]*d0[0]+d0[1]*d0[1]+d0[2]*d0[2],
                                            d1[0]*d1[0]+d1[1]*d1[1]+d1[2]*d1[2],
                                            dp[0]*dp[0]+dp[1]*dp[1]+dp[2]*dp[2]), sh);
    float inv0 = rsqrtf(ss.x * (1.0f / 768.0f) + 1e-5f);
    float inv1 = rsqrtf(ss.y * (1.0f / 768.0f) + 1e-5f);
    float invp = rsqrtf(ss.z * (1.0f / 768.0f) + 1e-5f);

    #pragma unroll
    for (int q = 0; q < 3; q++) {
        int i = threadIdx.x + q * 256;
        float wi = w[i], bi = b[i];
        float ln0 = d0[q] * inv0 * wi + bi;        // LN(row r0)
        float ln1 = d1[q] * inv1 * wi + bi;        // LN(row r1)
        float lnp = hasPrev ? (dp[q] * invp * wi + bi) : 0.0f;  // LN(row r0-1)
        float a = mk[i];
        oh[b0 + i] = __float2half(ln0 * a + lnp * (1.0f - a));
        oh[b1 + i] = __float2half(ln1 * a + ln0 * (1.0f - a));
        if (NMIX == 3) {
            float c = mv[i];
            oh[MD + b0 + i] = __float2half(ln0 * c + lnp * (1.0f - c));
            oh[MD + b1 + i] = __float2half(ln1 * c + ln0 * (1.0f - c));
        }
        float e = mr[i];
        int slot = (NMIX == 3) ? 2 : 1;
        oh[slot * MD + b0 + i] = __float2half(ln0 * e + lnp * (1.0f - e));
        oh[slot * MD + b1 + i] = __float2half(ln1 * e + ln0 * (1.0f - e));
    }
}

// ---------------- WKV sequential recurrence, 2 channels/thread -------------
// r is PRE-SIGMOIDED (done in the kvr GEMM epilogue).
__global__ void wkv_kernel(const float* __restrict__ k,
                           const float* __restrict__ v,
                           const float* __restrict__ r,
                           const float* __restrict__ tf,
                           const float* __restrict__ td,
                           __half* __restrict__ oh) {
    int ch0 = blockIdx.x * 64 + threadIdx.x;   // channels ch0 and ch0+32
    int ch1 = ch0 + 32;
    int b0 = ch0 / Dd, d0 = ch0 % Dd;
    int b1 = ch1 / Dd, d1 = ch1 % Dd;
    float tf0 = tf[d0], td0 = td[d0];
    float tf1 = tf[d1], td1 = td[d1];
    float aa0 = 0.f, bb0 = 0.f, pp0 = -1e30f;
    float aa1 = 0.f, bb1 = 0.f, pp1 = -1e30f;
    size_t base0 = (size_t)b0 * Tt * Dd + d0;
    size_t base1 = (size_t)b1 * Tt * Dd + d1;
    for (int t = 0; t < Tt; t++) {
        size_t o0 = base0 + (size_t)t * Dd;
        size_t o1 = base1 + (size_t)t * Dd;
        float k0 = k[o0], v0 = v[o0], r0 = r[o0];
        float k1 = k[o1], v1 = v[o1], r1 = r[o1];

        float w0 = tf0 + k0,              w1 = tf1 + k1;
        float p0 = fmaxf(pp0, w0),        p1 = fmaxf(pp1, w1);
        float e10 = __expf(pp0 - p0),     e11 = __expf(pp1 - p1);
        float e20 = __expf(w0 - p0),      e21 = __expf(w1 - p1);
        float wkv0 = __fdividef(e10 * aa0 + e20 * v0, e10 * bb0 + e20);
        float wkv1 = __fdividef(e11 * aa1 + e21 * v1, e11 * bb1 + e21);
        oh[o0] = __float2half(r0 * wkv0);
        oh[o1] = __float2half(r1 * wkv1);

        float x0 = pp0 + td0,             x1 = pp1 + td1;
        float q0 = fmaxf(x0, k0),         q1 = fmaxf(x1, k1);
        float f10 = __expf(x0 - q0),      f11 = __expf(x1 - q1);
        float f20 = __expf(k0 - q0),      f21 = __expf(k1 - q1);
        aa0 = f10 * aa0 + f20 * v0;       aa1 = f11 * aa1 + f21 * v1;
        bb0 = f10 * bb0 + f20;            bb1 = f11 * bb1 + f21;
        pp0 = q0;                         pp1 = q1;
    }
}

// ---------------- tensor-core GEMM: fp16 x fp16[K,N], fp32 acc -------------
// A: [M,lda] fp16 row-major. W: [K,ldb] fp16 row-major (N contiguous).
// BM=64, BN=128, BK=32; 256 threads = 8 warps (2m x 4n), warp tile 32x32.
// (Exact R11 configuration — best measured.)
// epi: 0 = store fp32; 2 = sqrelu -> fp16 (staged); 3 = sigmoid -> fp32
struct GArg {
    const __half *A, *W;
    float* C;
    __half* C2;
    int Ng, Kg, kOff, lda, ldb, epi;
};
struct GPack { GArg g[4]; };

#define BM 64
#define BN 128
#define BK 32
#define AST 40    // A row stride (halves)
#define BST 136   // B row stride (halves)

struct Stage {
    __half Ah[BM][AST];   // 5120 B
    __half Bw[BK][BST];   // 8704 B
};
// 3 stages = 41472 B; C staging (epi2) = 64*132*4 = 33792 B
#define GSMEM 41472

__global__ __launch_bounds__(256, 3)
void gemm_h(GPack pk) {
    GArg ga = pk.g[blockIdx.z];
    const int n0 = blockIdx.x * BN;
    if (n0 >= ga.Ng) return;

    extern __shared__ __align__(16) char smraw[];
    Stage* st = reinterpret_cast<Stage*>(smraw);
    float (*Csm)[BN + 4] = reinterpret_cast<float(*)[BN + 4]>(smraw);

    const int tid = threadIdx.x;
    const int wid = tid >> 5;
    const int wm = wid & 1;        // 0..1 -> 32 rows each
    const int wn = wid >> 1;       // 0..3 -> 32 cols each
    const int m0 = blockIdx.y * BM;

    const int ar = tid >> 2;           // 0..63
    const int ac = (tid & 3) * 8;      // 0,8,16,24
    const int br = tid >> 3;           // 0..31
    const int bc = (tid & 7) * 16;     // 0..112

    const __half* pA = ga.A + (size_t)(m0 + ar) * ga.lda + ga.kOff + ac;
    const __half* pW = ga.W + (size_t)(ga.kOff + br) * ga.ldb + n0 + bc;
    const size_t wstep = (size_t)ga.ldb;

    wmma::fragment<wmma::accumulator, 16, 16, 16, float> acc[2][2];
    #pragma unroll
    for (int i = 0; i < 2; i++)
        #pragma unroll
        for (int j = 0; j < 2; j++)
            wmma::fill_fragment(acc[i][j], 0.0f);

    const int nk = ga.Kg / BK;

    auto issue = [&](int s, int c) {
        int k0 = c * BK;
        cpa16(&st[s].Ah[ar][ac], pA + k0);
        cpa16(&st[s].Bw[br][bc],     pW + (size_t)k0 * wstep);
        cpa16(&st[s].Bw[br][bc + 8], pW + (size_t)k0 * wstep + 8);
        cp_commit();
    };

    issue(0, 0);
    if (nk > 1) issue(1, 1);

    for (int c = 0; c < nk; c++) {
        if (c + 1 < nk) cp_wait<1>(); else cp_wait<0>();
        __syncthreads();
        if (c + 2 < nk) issue((c + 2) % 3, c + 2);

        Stage& S = st[c % 3];
        #pragma unroll
        for (int kk = 0; kk < BK; kk += 16) {
            wmma::fragment<wmma::matrix_b, 16, 16, 16, __half, wmma::row_major> bf[2];
            #pragma unroll
            for (int j = 0; j < 2; j++)
                wmma::load_matrix_sync(bf[j], &S.Bw[kk][wn * 32 + j * 16], BST);

            wmma::fragment<wmma::matrix_a, 16, 16, 16, __half, wmma::row_major> af[2];
            #pragma unroll
            for (int i = 0; i < 2; i++)
                wmma::load_matrix_sync(af[i], &S.Ah[wm * 32 + i * 16][kk], AST);
            #pragma unroll
            for (int i = 0; i < 2; i++)
                #pragma unroll
                for (int j = 0; j < 2; j++)
                    wmma::mma_sync(acc[i][j], af[i], bf[j], acc[i][j]);
        }
    }

    const int Ng = ga.Ng, epi = ga.epi;

    if (epi == 2) {
        // staged epilogue (fp16 sqrelu out)
        __syncthreads();
        #pragma unroll
        for (int i = 0; i < 2; i++)
            #pragma unroll
            for (int j = 0; j < 2; j++)
                wmma::store_matrix_sync(&Csm[wm * 32 + i * 16][wn * 32 + j * 16],
                                        acc[i][j], BN + 4, wmma::mem_row_major);
        __syncthreads();
        const int ecol = tid & 127;
        const int erow = tid >> 7;
        #pragma unroll
        for (int i = 0; i < 32; i++) {
            int rr = i * 2 + erow;
            size_t idx = (size_t)(m0 + rr) * Ng + n0 + ecol;
            float t0 = fmaxf(Csm[rr][ecol], 0.0f);
            ga.C2[idx] = __float2half(t0 * t0);
        }
    } else {
        // direct fragment store (fp32 / sigmoid)
        if (epi == 3) {
            #pragma unroll
            for (int i = 0; i < 2; i++)
                #pragma unroll
                for (int j = 0; j < 2; j++)
                    #pragma unroll
                    for (int e = 0; e < acc[i][j].num_elements; e++)
                        acc[i][j].x[e] = __fdividef(1.0f, 1.0f + __expf(-acc[i][j].x[e]));
        }
        #pragma unroll
        for (int i = 0; i < 2; i++)
            #pragma unroll
            for (int j = 0; j < 2; j++)
                wmma::store_matrix_sync(
                    ga.C + (size_t)(m0 + wm * 32 + i * 16) * Ng + n0 + wn * 32 + j * 16,
                    acc[i][j], Ng, wmma::mem_row_major);
    }
}

// ---------------- host launcher ----------------
extern "C" void kernel_launch(void* const* d_in, const int* in_sizes, int n_in,
                              void* d_out, int out_size) {
    const int*   tokens     = (const int*)  d_in[0];
    const float* emb        = (const float*)d_in[1];
    const float* ln0_w      = (const float*)d_in[2];
    const float* ln0_b      = (const float*)d_in[3];
    const float* ln1_w      = (const float*)d_in[4];
    const float* ln1_b      = (const float*)d_in[5];
    const float* ln2_w      = (const float*)d_in[6];
    const float* ln2_b      = (const float*)d_in[7];
    const float* att_mix_k  = (const float*)d_in[8];
    const float* att_mix_v  = (const float*)d_in[9];
    const float* att_mix_r  = (const float*)d_in[10];
    const float* time_first = (const float*)d_in[11];
    const float* time_decay = (const float*)d_in[12];
    const float* att_Wk     = (const float*)d_in[13];
    const float* att_Wv     = (const float*)d_in[14];
    const float* att_Wr     = (const float*)d_in[15];
    const float* att_Wo     = (const float*)d_in[16];
    const float* ffn_mix_k  = (const float*)d_in[17];
    const float* ffn_mix_r  = (const float*)d_in[18];
    const float* ffn_Wk     = (const float*)d_in[19];
    const float* ffn_Wv     = (const float*)d_in[20];
    const float* ffn_Wr     = (const float*)d_in[21];
    const float* lnout_w    = (const float*)d_in[22];
    const float* lnout_b    = (const float*)d_in[23];
    float* out = (float*)d_out;

    float *xa, *xb, *kvr, *r2, *part;
    __half *mixh, *rwkvh, *hh, *w16;
    cudaGetSymbolAddress((void**)&xa,    g_x);
    cudaGetSymbolAddress((void**)&xb,    g_x2);
    cudaGetSymbolAddress((void**)&kvr,   g_kvr);
    cudaGetSymbolAddress((void**)&r2,    g_r2);
    cudaGetSymbolAddress((void**)&part,  g_part);
    cudaGetSymbolAddress((void**)&mixh,  g_mixh);
    cudaGetSymbolAddress((void**)&rwkvh, g_rwkvh);
    cudaGetSymbolAddress((void**)&hh,    g_hh);
    cudaGetSymbolAddress((void**)&w16,   g_w);

    cudaFuncSetAttribute(gemm_h, cudaFuncAttributeMaxDynamicSharedMemorySize, GSMEM);

    // ---- one fused conversion launch for all 7 weights ----
    {
        ConvArgs ca{};
        const float* srcs[7] = {att_Wk, att_Wv, att_Wr, att_Wo, ffn_Wk, ffn_Wv, ffn_Wr};
        size_t offs[7] = {OFF_WK, OFF_WV, OFF_WR, OFF_WO, OFF_FK, OFF_FV, OFF_FR};
        int ns[7] = {NDD, NDD, NDD, NDD, NDF, NDF, NDD};
        int cum = 0;
        for (int t = 0; t < 7; t++) {
            ca.src[t] = (const float4*)srcs[t];
            ca.dst[t] = (uint4*)(w16 + offs[t]);
            ca.n8[t] = ns[t] / 8;
            ca.cum[t] = cum;
            cum += (ca.n8[t] + 1023) / 1024;
        }
        ca.cum[7] = cum;
        convAll_kernel<<<cum, 256>>>(ca);
    }

    // x(a) = LN0(emb[tokens])
    embed_ln_kernel<<<MM, 256>>>(tokens, emb, ln0_w, ln0_b, xa);

    for (int l = 0; l < Ll; l++) {
        // ---- time mixing: [gated FV reduce +] LN1 + mix3 (2 rows/block) ----
        if (l == 0) {
            lnmix_kernel<3, 0><<<MM / 2, 256>>>(xa, nullptr, nullptr, nullptr, nullptr, nullptr,
                                                ln1_w, ln1_b,
                                                att_mix_k, att_mix_v, att_mix_r, mixh);
        } else {
            lnmix_kernel<3, 2><<<MM / 2, 256>>>(xb, r2, part, part + MD, part + 2 * MD, xa,
                                                ln1_w + l * Dd, ln1_b + l * Dd,
                                                att_mix_k + l * Dd, att_mix_v + l * Dd,
                                                att_mix_r + l * Dd, mixh);
        }
        // k/v/sigmoid(r) = mix @ {Wk,Wv,Wr}  (z=2 gets sigmoid epilogue)
        {
            GPack pk{};
            for (int z = 0; z < 3; z++) {
                pk.g[z].A = mixh + z * MD;
                size_t wo = (z == 0 ? OFF_WK : z == 1 ? OFF_WV : OFF_WR) + (size_t)l * Dd * Dd;
                pk.g[z].W = w16 + wo;
                pk.g[z].C = kvr + z * MD;
                pk.g[z].Ng = Dd; pk.g[z].Kg = Dd; pk.g[z].kOff = 0;
                pk.g[z].lda = Dd; pk.g[z].ldb = Dd;
                pk.g[z].epi = (z == 2) ? 3 : 0;
            }
            gemm_h<<<dim3(Dd / BN, MM / BM, 3), 256, GSMEM>>>(pk);
        }
        // sequential WKV (r pre-sigmoided), 2 channels/thread
        wkv_kernel<<<(Bb * Dd) / 64, 32>>>(kvr, kvr + MD, kvr + 2 * MD,
                                           time_first + l * Dd, time_decay + l * Dd, rwkvh);
        // Wo GEMM, split-K=3 -> partials
        {
            GPack pk{};
            for (int z = 0; z < 3; z++) {
                pk.g[z].A = rwkvh;
                pk.g[z].W = w16 + OFF_WO + (size_t)l * Dd * Dd;
                pk.g[z].C = part + z * MD;
                pk.g[z].Ng = Dd; pk.g[z].Kg = Dd / 3; pk.g[z].kOff = z * (Dd / 3);
                pk.g[z].lda = Dd; pk.g[z].ldb = Dd; pk.g[z].epi = 0;
            }
            gemm_h<<<dim3(Dd / BN, MM / BM, 3), 256, GSMEM>>>(pk);
        }
        // ---- channel mixing: Wo reduce + LN2 + mix2 (xa + parts -> xb) ----
        lnmix_kernel<2, 1><<<MM / 2, 256>>>(xa, nullptr, part, part + MD, part + 2 * MD, xb,
                                            ln2_w + l * Dd, ln2_b + l * Dd,
                                            ffn_mix_k + l * Dd, nullptr, ffn_mix_r + l * Dd, mixh);
        // FK: h = sqrelu(xk2 @ ffn_Wk) -> fp16
        {
            GPack pk{};
            pk.g[0].A = mixh;
            pk.g[0].W = w16 + OFF_FK + (size_t)l * Dd * Ff;
            pk.g[0].C2 = hh;
            pk.g[0].Ng = Ff; pk.g[0].Kg = Dd; pk.g[0].kOff = 0;
            pk.g[0].lda = Dd; pk.g[0].ldb = Ff; pk.g[0].epi = 2;
            gemm_h<<<dim3(Ff / BN, MM / BM, 1), 256, GSMEM>>>(pk);
        }
        // FV split-K=3 (z=0..2) batched with FR sigmoid (z=3)
        {
            GPack pk{};
            for (int z = 0; z < 3; z++) {
                pk.g[z].A = hh;
                pk.g[z].W = w16 + OFF_FV + (size_t)l * Ff * Dd;
                pk.g[z].C = part + z * MD;
                pk.g[z].Ng = Dd; pk.g[z].Kg = Ff / 3; pk.g[z].kOff = z * (Ff / 3);
                pk.g[z].lda = Ff; pk.g[z].ldb = Dd; pk.g[z].epi = 0;
            }
            pk.g[3].A = mixh + MD;
            pk.g[3].W = w16 + OFF_FR + (size_t)l * Dd * Dd;
            pk.g[3].C = r2;
            pk.g[3].Ng = Dd; pk.g[3].Kg = Dd; pk.g[3].kOff = 0;
            pk.g[3].lda = Dd; pk.g[3].ldb = Dd; pk.g[3].epi = 3;
            gemm_h<<<dim3(Dd / BN, MM / BM, 4), 256, GSMEM>>>(pk);
        }
    }

    // out = LN_out(xb + r2*(parts))
    ln_red_kernel<<<MM, 256>>>(xb, r2, part, part + MD, part + 2 * MD,
                               lnout_w, lnout_b, out);
}

// round 16
// speedup vs baseline: 1.2045x; 1.2045x over previous
#include <cuda_runtime.h>
#include <cuda_fp16.h>
#include <mma.h>
#include <math.h>
#include <cstdint>

using namespace nvcuda;

// Constants
#define Ll 12
#define Dd 768
#define Bb 4
#define Tt 256
#define Ff 3072
#define MM (Bb*Tt)   // 1024
#define MD (MM*Dd)

// fp16 weight offsets (elements), NATIVE [K,N] layout per layer slice
#define NDD (Ll*Dd*Dd)
#define NDF (Ll*Dd*Ff)
#define OFF_WK 0
#define OFF_WV (NDD)
#define OFF_WR (2*NDD)
#define OFF_WO (3*NDD)
#define OFF_FK (4*NDD)
#define OFF_FV (4*NDD + NDF)
#define OFF_FR (4*NDD + 2*NDF)
#define NWTOT  (4*NDD + 2*NDF + NDD)

// ---------------- scratch (device globals) ----------
__device__ __align__(256) float g_x[MD];        // residual ping
__device__ __align__(256) float g_x2[MD];       // residual pong
__device__ __align__(256) float g_kvr[3*MD];    // k, v, sigmoid(r)
__device__ __align__(256) float g_r2[MD];
__device__ __align__(256) float g_part[3*MD];
__device__ __align__(256) __half g_mixh[3*MD];  // mixed activations (fp16)
__device__ __align__(256) __half g_rwkvh[MD];
__device__ __align__(256) __half g_hh[MM*Ff];
__device__ __align__(256) __half g_w[NWTOT];    // W fp16 [K,N] native

// ---------------- cp.async helpers ----------------
__device__ __forceinline__ void cpa16(void* dst, const void* src) {
    unsigned d = (unsigned)__cvta_generic_to_shared(dst);
    asm volatile("cp.async.cg.shared.global [%0], [%1], 16;" :: "r"(d), "l"(src));
}
__device__ __forceinline__ void cp_commit() { asm volatile("cp.async.commit_group;"); }
template<int N> __device__ __forceinline__ void cp_wait() {
    asm volatile("cp.async.wait_group %0;" :: "n"(N));
}

// ---------------- fused streaming convert: all 7 weights, one launch -------
struct ConvArgs {
    const float4* src[7];
    uint4* dst[7];
    int n8[7];
    int cum[8];
};
__global__ void convAll_kernel(ConvArgs ca) {
    int blk = blockIdx.x;
    int y = 0;
    #pragma unroll
    for (int t = 1; t < 7; t++)
        if (blk >= ca.cum[t]) y = t;
    int local = blk - ca.cum[y];
    const float4* W = ca.src[y];
    uint4* out = ca.dst[y];
    int n8 = ca.n8[y];
    int i = local * 1024 + threadIdx.x;
    #pragma unroll
    for (int u = 0; u < 4; u++, i += 256) {
        if (i < n8) {
            float4 a = W[2*i], b = W[2*i+1];
            __half2 h0 = __floats2half2_rn(a.x, a.y);
            __half2 h1 = __floats2half2_rn(a.z, a.w);
            __half2 h2 = __floats2half2_rn(b.x, b.y);
            __half2 h3 = __floats2half2_rn(b.z, b.w);
            uint4 o;
            o.x = *(unsigned*)&h0; o.y = *(unsigned*)&h1;
            o.z = *(unsigned*)&h2; o.w = *(unsigned*)&h3;
            out[i] = o;
        }
    }
}

// ---------------- block reduces ----------------
__device__ __forceinline__ float blockReduceSum(float v, float* sh) {
    int lane = threadIdx.x & 31, w = threadIdx.x >> 5;
    #pragma unroll
    for (int o = 16; o; o >>= 1) v += __shfl_xor_sync(0xffffffffu, v, o);
    if (lane == 0) sh[w] = v;
    __syncthreads();
    float r;
    if (threadIdx.x < 8) {
        r = sh[threadIdx.x];
        #pragma unroll
        for (int o = 4; o; o >>= 1) r += __shfl_xor_sync(0x000000ffu, r, o);
        if (threadIdx.x == 0) sh[0] = r;
    }
    __syncthreads();
    r = sh[0];
    __syncthreads();
    return r;
}
__device__ __forceinline__ float3 blockReduceSum3(float3 v, float3* sh) {
    int lane = threadIdx.x & 31, w = threadIdx.x >> 5;
    #pragma unroll
    for (int o = 16; o; o >>= 1) {
        v.x += __shfl_xor_sync(0xffffffffu, v.x, o);
        v.y += __shfl_xor_sync(0xffffffffu, v.y, o);
        v.z += __shfl_xor_sync(0xffffffffu, v.z, o);
    }
    if (lane == 0) sh[w] = v;
    __syncthreads();
    float3 r;
    if (threadIdx.x < 8) {
        r = sh[threadIdx.x];
        #pragma unroll
        for (int o = 4; o; o >>= 1) {
            r.x += __shfl_xor_sync(0x000000ffu, r.x, o);
            r.y += __shfl_xor_sync(0x000000ffu, r.y, o);
            r.z += __shfl_xor_sync(0x000000ffu, r.z, o);
        }
        if (threadIdx.x == 0) sh[0] = r;
    }
    __syncthreads();
    r = sh[0];
    __syncthreads();
    return r;
}

// ---------------- embedding gather + LN (ln0) ----------------
__global__ void embed_ln_kernel(const int* __restrict__ tokens,
                                const float* __restrict__ emb,
                                const float* __restrict__ w,
                                const float* __restrict__ b,
                                float* __restrict__ Y) {
    __shared__ float sh[8];
    int m = blockIdx.x;
    int tok = tokens[m];
    const float* xr = emb + (size_t)tok * Dd;
    int i0 = threadIdx.x, i1 = i0 + 256, i2 = i0 + 512;
    float v0 = xr[i0], v1 = xr[i1], v2 = xr[i2];
    float s = blockReduceSum(v0 + v1 + v2, sh);
    float mu = s * (1.0f / 768.0f);
    float c0 = v0 - mu, c1 = v1 - mu, c2 = v2 - mu;
    float ss = blockReduceSum(c0*c0 + c1*c1 + c2*c2, sh);
    float inv = rsqrtf(ss * (1.0f / 768.0f) + 1e-5f);
    float* yr = Y + (size_t)m * Dd;
    yr[i0] = c0 * inv * w[i0] + b[i0];
    yr[i1] = c1 * inv * w[i1] + b[i1];
    yr[i2] = c2 * inv * w[i2] + b[i2];
}

// ---------------- final LN with fused gated split-K reduction --------------
__global__ void ln_red_kernel(const float* __restrict__ X,
                              const float* __restrict__ g,
                              const float* __restrict__ q0,
                              const float* __restrict__ q1,
                              const float* __restrict__ q2,
                              const float* __restrict__ w,
                              const float* __restrict__ b,
                              float* __restrict__ Y) {
    __shared__ float sh[8];
    int m = blockIdx.x;
    size_t base = (size_t)m * Dd;
    int i0 = threadIdx.x, i1 = i0 + 256, i2 = i0 + 512;
    float v0 = X[base+i0] + g[base+i0] * (q0[base+i0] + q1[base+i0] + q2[base+i0]);
    float v1 = X[base+i1] + g[base+i1] * (q0[base+i1] + q1[base+i1] + q2[base+i1]);
    float v2 = X[base+i2] + g[base+i2] * (q0[base+i2] + q1[base+i2] + q2[base+i2]);
    float s = blockReduceSum(v0 + v1 + v2, sh);
    float mu = s * (1.0f / 768.0f);
    float c0 = v0 - mu, c1 = v1 - mu, c2 = v2 - mu;
    float ss = blockReduceSum(c0*c0 + c1*c1 + c2*c2, sh);
    float inv = rsqrtf(ss * (1.0f / 768.0f) + 1e-5f);
    float* yr = Y + base;
    yr[i0] = c0 * inv * w[i0] + b[i0];
    yr[i1] = c1 * inv * w[i1] + b[i1];
    yr[i2] = c2 * inv * w[i2] + b[i2];
}

// ------- fused [split-K reduce +] LN + token-shift mix, 2 rows/block -------
// RED: 0 = none; 1 = x += q0+q1+q2; 2 = x += gate*(q0+q1+q2)
template<int NMIX, int RED>
__global__ void lnmix_kernel(const float* __restrict__ X,
                             const float* __restrict__ gate,
                             const float* __restrict__ q0,
                             const float* __restrict__ q1,
                             const float* __restrict__ q2,
                             float* __restrict__ Xout,
                             const float* __restrict__ w,
                             const float* __restrict__ b,
                             const float* __restrict__ mk,
                             const float* __restrict__ mv,
                             const float* __restrict__ mr,
                             __half* __restrict__ oh) {
    __shared__ float3 sh[8];
    int r0 = blockIdx.x * 2;
    bool hasPrev = (r0 & (Tt - 1)) != 0;
    size_t b0 = (size_t)r0 * Dd;
    size_t b1 = b0 + Dd;
    size_t bp = b0 - Dd;

    float c0[3], c1[3], pv[3];
    #pragma unroll
    for (int q = 0; q < 3; q++) {
        int i = threadIdx.x + q * 256;
        float v0 = X[b0 + i];
        float v1 = X[b1 + i];
        if (RED == 1) {
            v0 += q0[b0+i] + q1[b0+i] + q2[b0+i];
            v1 += q0[b1+i] + q1[b1+i] + q2[b1+i];
        } else if (RED == 2) {
            v0 += gate[b0+i] * (q0[b0+i] + q1[b0+i] + q2[b0+i]);
            v1 += gate[b1+i] * (q0[b1+i] + q1[b1+i] + q2[b1+i]);
        }
        if (RED) { Xout[b0 + i] = v0; Xout[b1 + i] = v1; }
        c0[q] = v0; c1[q] = v1;
        float p = 0.0f;
        if (hasPrev) {
            p = X[bp + i];
            if (RED == 1) p += q0[bp+i] + q1[bp+i] + q2[bp+i];
            else if (RED == 2) p += gate[bp+i] * (q0[bp+i] + q1[bp+i] + q2[bp+i]);
        }
        pv[q] = p;
    }

    float3 s = blockReduceSum3(make_float3(c0[0]+c0[1]+c0[2],
                                           c1[0]+c1[1]+c1[2],
                                           pv[0]+pv[1]+pv[2]), sh);
    float mu0 = s.x * (1.0f / 768.0f);
    float mu1 = s.y * (1.0f / 768.0f);
    float mup = s.z * (1.0f / 768.0f);
    float d0[3], d1[3], dp[3];
    #pragma unroll
    for (int q = 0; q < 3; q++) { d0[q] = c0[q] - mu0; d1[q] = c1[q] - mu1; dp[q] = pv[q] - mup; }
    float3 ss = blockReduceSum3(make_float3(d0[0]*d0[0]+d0[1]*d0[1]+d0[2]*d0[2],
                                            d1[0]*d1[0]+d1[1]*d1[1]+d1[2]*d1[2],
                                            dp[0]*dp[0]+dp[1]*dp[1]+dp[2]*dp[2]), sh);
    float inv0 = rsqrtf(ss.x * (1.0f / 768.0f) + 1e-5f);
    float inv1 = rsqrtf(ss.y * (1.0f / 768.0f) + 1e-5f);
    float invp = rsqrtf(ss.z * (1.0f / 768.0f) + 1e-5f);

    #pragma unroll
    for (int q = 0; q < 3; q++) {
        int i = threadIdx.x + q * 256;
        float wi = w[i], bi = b[i];
        float ln0 = d0[q] * inv0 * wi + bi;
        float ln1 = d1[q] * inv1 * wi + bi;
        float lnp = hasPrev ? (dp[q] * invp * wi + bi) : 0.0f;
        float a = mk[i];
        oh[b0 + i] = __float2half(ln0 * a + lnp * (1.0f - a));
        oh[b1 + i] = __float2half(ln1 * a + ln0 * (1.0f - a));
        if (NMIX == 3) {
            float c = mv[i];
            oh[MD + b0 + i] = __float2half(ln0 * c + lnp * (1.0f - c));
            oh[MD + b1 + i] = __float2half(ln1 * c + ln0 * (1.0f - c));
        }
        float e = mr[i];
        int slot = (NMIX == 3) ? 2 : 1;
        oh[slot * MD + b0 + i] = __float2half(ln0 * e + lnp * (1.0f - e));
        oh[slot * MD + b1 + i] = __float2half(ln1 * e + ln0 * (1.0f - e));
    }
}

// -------- WKV sequential recurrence, 2 channels/thread, prefetch d=2 -------
// r is PRE-SIGMOIDED (done in the kvr GEMM epilogue).
__global__ void wkv_kernel(const float* __restrict__ k,
                           const float* __restrict__ v,
                           const float* __restrict__ r,
                           const float* __restrict__ tf,
                           const float* __restrict__ td,
                           __half* __restrict__ oh) {
    int ch0 = blockIdx.x * 64 + threadIdx.x;   // channels ch0 and ch0+32
    int ch1 = ch0 + 32;
    int b0 = ch0 / Dd, d0 = ch0 % Dd;
    int b1 = ch1 / Dd, d1 = ch1 % Dd;
    float tf0 = tf[d0], td0 = td[d0];
    float tf1 = tf[d1], td1 = td[d1];
    float aa0 = 0.f, bb0 = 0.f, pp0 = -1e30f;
    float aa1 = 0.f, bb1 = 0.f, pp1 = -1e30f;
    size_t base0 = (size_t)b0 * Tt * Dd + d0;
    size_t base1 = (size_t)b1 * Tt * Dd + d1;

    // distance-2 prefetch buffers for both chains
    float kA[2], vA[2], rA[2], kB[2], vB[2], rB[2];
    kA[0] = k[base0];      vA[0] = v[base0];      rA[0] = r[base0];
    kA[1] = k[base0 + Dd]; vA[1] = v[base0 + Dd]; rA[1] = r[base0 + Dd];
    kB[0] = k[base1];      vB[0] = v[base1];      rB[0] = r[base1];
    kB[1] = k[base1 + Dd]; vB[1] = v[base1 + Dd]; rB[1] = r[base1 + Dd];

    for (int t = 0; t < Tt; t++) {
        int s = t & 1;
        float k0 = kA[s], v0 = vA[s], r0 = rA[s];
        float k1 = kB[s], v1 = vB[s], r1 = rB[s];
        if (t + 2 < Tt) {
            size_t n0 = base0 + (size_t)(t + 2) * Dd;
            size_t n1 = base1 + (size_t)(t + 2) * Dd;
            kA[s] = k[n0]; vA[s] = v[n0]; rA[s] = r[n0];
            kB[s] = k[n1]; vB[s] = v[n1]; rB[s] = r[n1];
        }

        float w0 = tf0 + k0,              w1 = tf1 + k1;
        float p0 = fmaxf(pp0, w0),        p1 = fmaxf(pp1, w1);
        float e10 = __expf(pp0 - p0),     e11 = __expf(pp1 - p1);
        float e20 = __expf(w0 - p0),      e21 = __expf(w1 - p1);
        float wkv0 = __fdividef(e10 * aa0 + e20 * v0, e10 * bb0 + e20);
        float wkv1 = __fdividef(e11 * aa1 + e21 * v1, e11 * bb1 + e21);
        oh[base0 + (size_t)t * Dd] = __float2half(r0 * wkv0);
        oh[base1 + (size_t)t * Dd] = __float2half(r1 * wkv1);

        float x0 = pp0 + td0,             x1 = pp1 + td1;
        float q0 = fmaxf(x0, k0),         q1 = fmaxf(x1, k1);
        float f10 = __expf(x0 - q0),      f11 = __expf(x1 - q1);
        float f20 = __expf(k0 - q0),      f21 = __expf(k1 - q1);
        aa0 = f10 * aa0 + f20 * v0;       aa1 = f11 * aa1 + f21 * v1;
        bb0 = f10 * bb0 + f20;            bb1 = f11 * bb1 + f21;
        pp0 = q0;                         pp1 = q1;
    }
}

// ---------------- tensor-core GEMM: fp16 x fp16[K,N], fp32 acc -------------
// BM=64, BN=128, BK=32; 256 threads = 8 warps (2m x 4n), warp tile 32x32.
// (Exact R11 configuration — best measured.)
// epi: 0 = store fp32; 2 = sqrelu -> fp16 (staged); 3 = sigmoid -> fp32
struct GArg {
    const __half *A, *W;
    float* C;
    __half* C2;
    int Ng, Kg, kOff, lda, ldb, epi;
};
struct GPack { GArg g[4]; };

#define BM 64
#define BN 128
#define BK 32
#define AST 40    // A row stride (halves)
#define BST 136   // B row stride (halves)

struct Stage {
    __half Ah[BM][AST];   // 5120 B
    __half Bw[BK][BST];   // 8704 B
};
#define GSMEM 41472

__global__ __launch_bounds__(256, 3)
void gemm_h(GPack pk) {
    GArg ga = pk.g[blockIdx.z];
    const int n0 = blockIdx.x * BN;
    if (n0 >= ga.Ng) return;

    extern __shared__ __align__(16) char smraw[];
    Stage* st = reinterpret_cast<Stage*>(smraw);
    float (*Csm)[BN + 4] = reinterpret_cast<float(*)[BN + 4]>(smraw);

    const int tid = threadIdx.x;
    const int wid = tid >> 5;
    const int wm = wid & 1;
    const int wn = wid >> 1;
    const int m0 = blockIdx.y * BM;

    const int ar = tid >> 2;
    const int ac = (tid & 3) * 8;
    const int br = tid >> 3;
    const int bc = (tid & 7) * 16;

    const __half* pA = ga.A + (size_t)(m0 + ar) * ga.lda + ga.kOff + ac;
    const __half* pW = ga.W + (size_t)(ga.kOff + br) * ga.ldb + n0 + bc;
    const size_t wstep = (size_t)ga.ldb;

    wmma::fragment<wmma::accumulator, 16, 16, 16, float> acc[2][2];
    #pragma unroll
    for (int i = 0; i < 2; i++)
        #pragma unroll
        for (int j = 0; j < 2; j++)
            wmma::fill_fragment(acc[i][j], 0.0f);

    const int nk = ga.Kg / BK;

    auto issue = [&](int s, int c) {
        int k0 = c * BK;
        cpa16(&st[s].Ah[ar][ac], pA + k0);
        cpa16(&st[s].Bw[br][bc],     pW + (size_t)k0 * wstep);
        cpa16(&st[s].Bw[br][bc + 8], pW + (size_t)k0 * wstep + 8);
        cp_commit();
    };

    issue(0, 0);
    if (nk > 1) issue(1, 1);

    for (int c = 0; c < nk; c++) {
        if (c + 1 < nk) cp_wait<1>(); else cp_wait<0>();
        __syncthreads();
        if (c + 2 < nk) issue((c + 2) % 3, c + 2);

        Stage& S = st[c % 3];
        #pragma unroll
        for (int kk = 0; kk < BK; kk += 16) {
            wmma::fragment<wmma::matrix_b, 16, 16, 16, __half, wmma::row_major> bf[2];
            #pragma unroll
            for (int j = 0; j < 2; j++)
                wmma::load_matrix_sync(bf[j], &S.Bw[kk][wn * 32 + j * 16], BST);

            wmma::fragment<wmma::matrix_a, 16, 16, 16, __half, wmma::row_major> af[2];
            #pragma unroll
            for (int i = 0; i < 2; i++)
                wmma::load_matrix_sync(af[i], &S.Ah[wm * 32 + i * 16][kk], AST);
            #pragma unroll
            for (int i = 0; i < 2; i++)
                #pragma unroll
                for (int j = 0; j < 2; j++)
                    wmma::mma_sync(acc[i][j], af[i], bf[j], acc[i][j]);
        }
    }

    const int Ng = ga.Ng, epi = ga.epi;

    if (epi == 2) {
        __syncthreads();
        #pragma unroll
        for (int i = 0; i < 2; i++)
            #pragma unroll
            for (int j = 0; j < 2; j++)
                wmma::store_matrix_sync(&Csm[wm * 32 + i * 16][wn * 32 + j * 16],
                                        acc[i][j], BN + 4, wmma::mem_row_major);
        __syncthreads();
        const int ecol = tid & 127;
        const int erow = tid >> 7;
        #pragma unroll
        for (int i = 0; i < 32; i++) {
            int rr = i * 2 + erow;
            size_t idx = (size_t)(m0 + rr) * Ng + n0 + ecol;
            float t0 = fmaxf(Csm[rr][ecol], 0.0f);
            ga.C2[idx] = __float2half(t0 * t0);
        }
    } else {
        if (epi == 3) {
            #pragma unroll
            for (int i = 0; i < 2; i++)
                #pragma unroll
                for (int j = 0; j < 2; j++)
                    #pragma unroll
                    for (int e = 0; e < acc[i][j].num_elements; e++)
                        acc[i][j].x[e] = __fdividef(1.0f, 1.0f + __expf(-acc[i][j].x[e]));
        }
        #pragma unroll
        for (int i = 0; i < 2; i++)
            #pragma unroll
            for (int j = 0; j < 2; j++)
                wmma::store_matrix_sync(
                    ga.C + (size_t)(m0 + wm * 32 + i * 16) * Ng + n0 + wn * 32 + j * 16,
                    acc[i][j], Ng, wmma::mem_row_major);
    }
}

// ---------------- host launcher ----------------
extern "C" void kernel_launch(void* const* d_in, const int* in_sizes, int n_in,
                              void* d_out, int out_size) {
    const int*   tokens     = (const int*)  d_in[0];
    const float* emb        = (const float*)d_in[1];
    const float* ln0_w      = (const float*)d_in[2];
    const float* ln0_b      = (const float*)d_in[3];
    const float* ln1_w      = (const float*)d_in[4];
    const float* ln1_b      = (const float*)d_in[5];
    const float* ln2_w      = (const float*)d_in[6];
    const float* ln2_b      = (const float*)d_in[7];
    const float* att_mix_k  = (const float*)d_in[8];
    const float* att_mix_v  = (const float*)d_in[9];
    const float* att_mix_r  = (const float*)d_in[10];
    const float* time_first = (const float*)d_in[11];
    const float* time_decay = (const float*)d_in[12];
    const float* att_Wk     = (const float*)d_in[13];
    const float* att_Wv     = (const float*)d_in[14];
    const float* att_Wr     = (const float*)d_in[15];
    const float* att_Wo     = (const float*)d_in[16];
    const float* ffn_mix_k  = (const float*)d_in[17];
    const float* ffn_mix_r  = (const float*)d_in[18];
    const float* ffn_Wk     = (const float*)d_in[19];
    const float* ffn_Wv     = (const float*)d_in[20];
    const float* ffn_Wr     = (const float*)d_in[21];
    const float* lnout_w    = (const float*)d_in[22];
    const float* lnout_b    = (const float*)d_in[23];
    float* out = (float*)d_out;

    float *xa, *xb, *kvr, *r2, *part;
    __half *mixh, *rwkvh, *hh, *w16;
    cudaGetSymbolAddress((void**)&xa,    g_x);
    cudaGetSymbolAddress((void**)&xb,    g_x2);
    cudaGetSymbolAddress((void**)&kvr,   g_kvr);
    cudaGetSymbolAddress((void**)&r2,    g_r2);
    cudaGetSymbolAddress((void**)&part,  g_part);
    cudaGetSymbolAddress((void**)&mixh,  g_mixh);
    cudaGetSymbolAddress((void**)&rwkvh, g_rwkvh);
    cudaGetSymbolAddress((void**)&hh,    g_hh);
    cudaGetSymbolAddress((void**)&w16,   g_w);

    cudaFuncSetAttribute(gemm_h, cudaFuncAttributeMaxDynamicSharedMemorySize, GSMEM);

    // ---- one fused conversion launch for all 7 weights ----
    {
        ConvArgs ca{};
        const float* srcs[7] = {att_Wk, att_Wv, att_Wr, att_Wo, ffn_Wk, ffn_Wv, ffn_Wr};
        size_t offs[7] = {OFF_WK, OFF_WV, OFF_WR, OFF_WO, OFF_FK, OFF_FV, OFF_FR};
        int ns[7] = {NDD, NDD, NDD, NDD, NDF, NDF, NDD};
        int cum = 0;
        for (int t = 0; t < 7; t++) {
            ca.src[t] = (const float4*)srcs[t];
            ca.dst[t] = (uint4*)(w16 + offs[t]);
            ca.n8[t] = ns[t] / 8;
            ca.cum[t] = cum;
            cum += (ca.n8[t] + 1023) / 1024;
        }
        ca.cum[7] = cum;
        convAll_kernel<<<cum, 256>>>(ca);
    }

    // x(a) = LN0(emb[tokens])
    embed_ln_kernel<<<MM, 256>>>(tokens, emb, ln0_w, ln0_b, xa);

    for (int l = 0; l < Ll; l++) {
        // ---- time mixing: [gated FV reduce +] LN1 + mix3 (2 rows/block) ----
        if (l == 0) {
            lnmix_kernel<3, 0><<<MM / 2, 256>>>(xa, nullptr, nullptr, nullptr, nullptr, nullptr,
                                                ln1_w, ln1_b,
                                                att_mix_k, att_mix_v, att_mix_r, mixh);
        } else {
            lnmix_kernel<3, 2><<<MM / 2, 256>>>(xb, r2, part, part + MD, part + 2 * MD, xa,
                                                ln1_w + l * Dd, ln1_b + l * Dd,
                                                att_mix_k + l * Dd, att_mix_v + l * Dd,
                                                att_mix_r + l * Dd, mixh);
        }
        // k/v/sigmoid(r) = mix @ {Wk,Wv,Wr}  (z=2 gets sigmoid epilogue)
        {
            GPack pk{};
            for (int z = 0; z < 3; z++) {
                pk.g[z].A = mixh + z * MD;
                size_t wo = (z == 0 ? OFF_WK : z == 1 ? OFF_WV : OFF_WR) + (size_t)l * Dd * Dd;
                pk.g[z].W = w16 + wo;
                pk.g[z].C = kvr + z * MD;
                pk.g[z].Ng = Dd; pk.g[z].Kg = Dd; pk.g[z].kOff = 0;
                pk.g[z].lda = Dd; pk.g[z].ldb = Dd;
                pk.g[z].epi = (z == 2) ? 3 : 0;
            }
            gemm_h<<<dim3(Dd / BN, MM / BM, 3), 256, GSMEM>>>(pk);
        }
        // sequential WKV (r pre-sigmoided), 2 channels/thread, prefetch d=2
        wkv_kernel<<<(Bb * Dd) / 64, 32>>>(kvr, kvr + MD, kvr + 2 * MD,
                                           time_first + l * Dd, time_decay + l * Dd, rwkvh);
        // Wo GEMM, split-K=3 -> partials
        {
            GPack pk{};
            for (int z = 0; z < 3; z++) {
                pk.g[z].A = rwkvh;
                pk.g[z].W = w16 + OFF_WO + (size_t)l * Dd * Dd;
                pk.g[z].C = part + z * MD;
                pk.g[z].Ng = Dd; pk.g[z].Kg = Dd / 3; pk.g[z].kOff = z * (Dd / 3);
                pk.g[z].lda = Dd; pk.g[z].ldb = Dd; pk.g[z].epi = 0;
            }
            gemm_h<<<dim3(Dd / BN, MM / BM, 3), 256, GSMEM>>>(pk);
        }
        // ---- channel mixing: Wo reduce + LN2 + mix2 (xa + parts -> xb) ----
        lnmix_kernel<2, 1><<<MM / 2, 256>>>(xa, nullptr, part, part + MD, part + 2 * MD, xb,
                                            ln2_w + l * Dd, ln2_b + l * Dd,
                                            ffn_mix_k + l * Dd, nullptr, ffn_mix_r + l * Dd, mixh);
        // FK: h = sqrelu(xk2 @ ffn_Wk) -> fp16
        {
            GPack pk{};
            pk.g[0].A = mixh;
            pk.g[0].W = w16 + OFF_FK + (size_t)l * Dd * Ff;
            pk.g[0].C2 = hh;
            pk.g[0].Ng = Ff; pk.g[0].Kg = Dd; pk.g[0].kOff = 0;
            pk.g[0].lda = Dd; pk.g[0].ldb = Ff; pk.g[0].epi = 2;
            gemm_h<<<dim3(Ff / BN, MM / BM, 1), 256, GSMEM>>>(pk);
        }
        // FV split-K=3 (z=0..2) batched with FR sigmoid (z=3)
        {
            GPack pk{};
            for (int z = 0; z < 3; z++) {
                pk.g[z].A = hh;
                pk.g[z].W = w16 + OFF_FV + (size_t)l * Ff * Dd;
                pk.g[z].C = part + z * MD;
                pk.g[z].Ng = Dd; pk.g[z].Kg = Ff / 3; pk.g[z].kOff = z * (Ff / 3);
                pk.g[z].lda = Ff; pk.g[z].ldb = Dd; pk.g[z].epi = 0;
            }
            pk.g[3].A = mixh + MD;
            pk.g[3].W = w16 + OFF_FR + (size_t)l * Dd * Dd;
            pk.g[3].C = r2;
            pk.g[3].Ng = Dd; pk.g[3].Kg = Dd; pk.g[3].kOff = 0;
            pk.g[3].lda = Dd; pk.g[3].ldb = Dd; pk.g[3].epi = 3;
            gemm_h<<<dim3(Dd / BN, MM / BM, 4), 256, GSMEM>>>(pk);
        }
    }

    // out = LN_out(xb + r2*(parts))
    ln_red_kernel<<<MM, 256>>>(xb, r2, part, part + MD, part + 2 * MD,
                               lnout_w, lnout_b, out);
}

// round 17
// speedup vs baseline: 1.3873x; 1.1518x over previous
#include <cuda_runtime.h>
#include <cuda_fp16.h>
#include <mma.h>
#include <math.h>
#include <cstdint>

using namespace nvcuda;

// Constants
#define Ll 12
#define Dd 768
#define Bb 4
#define Tt 256
#define Ff 3072
#define MM (Bb*Tt)   // 1024
#define MD (MM*Dd)

// fp16 weight offsets (elements), NATIVE [K,N] layout per layer slice
#define NDD (Ll*Dd*Dd)
#define NDF (Ll*Dd*Ff)
#define OFF_WK 0
#define OFF_WV (NDD)
#define OFF_WR (2*NDD)
#define OFF_WO (3*NDD)
#define OFF_FK (4*NDD)
#define OFF_FV (4*NDD + NDF)
#define OFF_FR (4*NDD + 2*NDF)
#define NWTOT  (4*NDD + 2*NDF + NDD)

// ---------------- scratch (device globals) ----------
__device__ __align__(256) float g_x[MD];        // residual ping
__device__ __align__(256) float g_x2[MD];       // residual pong
__device__ __align__(256) float g_kvr[3*MD];
__device__ __align__(256) float g_r2[MD];
__device__ __align__(256) float g_part[3*MD];
__device__ __align__(256) __half g_mixh[3*MD];  // mixed activations (fp16)
__device__ __align__(256) __half g_rwkvh[MD];
__device__ __align__(256) __half g_hh[MM*Ff];
__device__ __align__(256) __half g_w[NWTOT];    // W fp16 [K,N] native

// ---------------- cp.async helpers ----------------
__device__ __forceinline__ void cpa16(void* dst, const void* src) {
    unsigned d = (unsigned)__cvta_generic_to_shared(dst);
    asm volatile("cp.async.cg.shared.global [%0], [%1], 16;" :: "r"(d), "l"(src));
}
__device__ __forceinline__ void cp_commit() { asm volatile("cp.async.commit_group;"); }
template<int N> __device__ __forceinline__ void cp_wait() {
    asm volatile("cp.async.wait_group %0;" :: "n"(N));
}

// ---------------- fused streaming convert: all 7 weights, one launch -------
struct ConvArgs {
    const float4* src[7];
    uint4* dst[7];
    int n8[7];
    int cum[8];
};
__global__ void convAll_kernel(ConvArgs ca) {
    int blk = blockIdx.x;
    int y = 0;
    #pragma unroll
    for (int t = 1; t < 7; t++)
        if (blk >= ca.cum[t]) y = t;
    int local = blk - ca.cum[y];
    const float4* W = ca.src[y];
    uint4* out = ca.dst[y];
    int n8 = ca.n8[y];
    int i = local * 1024 + threadIdx.x;
    #pragma unroll
    for (int u = 0; u < 4; u++, i += 256) {
        if (i < n8) {
            float4 a = W[2*i], b = W[2*i+1];
            __half2 h0 = __floats2half2_rn(a.x, a.y);
            __half2 h1 = __floats2half2_rn(a.z, a.w);
            __half2 h2 = __floats2half2_rn(b.x, b.y);
            __half2 h3 = __floats2half2_rn(b.z, b.w);
            uint4 o;
            o.x = *(unsigned*)&h0; o.y = *(unsigned*)&h1;
            o.z = *(unsigned*)&h2; o.w = *(unsigned*)&h3;
            out[i] = o;
        }
    }
}

// ---------------- block reduces ----------------
__device__ __forceinline__ float blockReduceSum(float v, float* sh) {
    int lane = threadIdx.x & 31, w = threadIdx.x >> 5;
    #pragma unroll
    for (int o = 16; o; o >>= 1) v += __shfl_xor_sync(0xffffffffu, v, o);
    if (lane == 0) sh[w] = v;
    __syncthreads();
    float r;
    if (threadIdx.x < 8) {
        r = sh[threadIdx.x];
        #pragma unroll
        for (int o = 4; o; o >>= 1) r += __shfl_xor_sync(0x000000ffu, r, o);
        if (threadIdx.x == 0) sh[0] = r;
    }
    __syncthreads();
    r = sh[0];
    __syncthreads();
    return r;
}
__device__ __forceinline__ float2 blockReduceSum2(float2 v, float2* sh) {
    int lane = threadIdx.x & 31, w = threadIdx.x >> 5;
    #pragma unroll
    for (int o = 16; o; o >>= 1) {
        v.x += __shfl_xor_sync(0xffffffffu, v.x, o);
        v.y += __shfl_xor_sync(0xffffffffu, v.y, o);
    }
    if (lane == 0) sh[w] = v;
    __syncthreads();
    float2 r;
    if (threadIdx.x < 8) {
        r = sh[threadIdx.x];
        #pragma unroll
        for (int o = 4; o; o >>= 1) {
            r.x += __shfl_xor_sync(0x000000ffu, r.x, o);
            r.y += __shfl_xor_sync(0x000000ffu, r.y, o);
        }
        if (threadIdx.x == 0) sh[0] = r;
    }
    __syncthreads();
    r = sh[0];
    __syncthreads();
    return r;
}

// ---------------- embedding gather + LN (ln0) ----------------
__global__ void embed_ln_kernel(const int* __restrict__ tokens,
                                const float* __restrict__ emb,
                                const float* __restrict__ w,
                                const float* __restrict__ b,
                                float* __restrict__ Y) {
    __shared__ float sh[8];
    int m = blockIdx.x;
    int tok = tokens[m];
    const float* xr = emb + (size_t)tok * Dd;
    int i0 = threadIdx.x, i1 = i0 + 256, i2 = i0 + 512;
    float v0 = xr[i0], v1 = xr[i1], v2 = xr[i2];
    float s = blockReduceSum(v0 + v1 + v2, sh);
    float mu = s * (1.0f / 768.0f);
    float c0 = v0 - mu, c1 = v1 - mu, c2 = v2 - mu;
    float ss = blockReduceSum(c0*c0 + c1*c1 + c2*c2, sh);
    float inv = rsqrtf(ss * (1.0f / 768.0f) + 1e-5f);
    float* yr = Y + (size_t)m * Dd;
    yr[i0] = c0 * inv * w[i0] + b[i0];
    yr[i1] = c1 * inv * w[i1] + b[i1];
    yr[i2] = c2 * inv * w[i2] + b[i2];
}

// ---------------- final LN with fused gated split-K reduction --------------
__global__ void ln_red_kernel(const float* __restrict__ X,
                              const float* __restrict__ g,
                              const float* __restrict__ q0,
                              const float* __restrict__ q1,
                              const float* __restrict__ q2,
                              const float* __restrict__ w,
                              const float* __restrict__ b,
                              float* __restrict__ Y) {
    __shared__ float sh[8];
    int m = blockIdx.x;
    size_t base = (size_t)m * Dd;
    int i0 = threadIdx.x, i1 = i0 + 256, i2 = i0 + 512;
    float v0 = X[base+i0] + g[base+i0] * (q0[base+i0] + q1[base+i0] + q2[base+i0]);
    float v1 = X[base+i1] + g[base+i1] * (q0[base+i1] + q1[base+i1] + q2[base+i1]);
    float v2 = X[base+i2] + g[base+i2] * (q0[base+i2] + q1[base+i2] + q2[base+i2]);
    float s = blockReduceSum(v0 + v1 + v2, sh);
    float mu = s * (1.0f / 768.0f);
    float c0 = v0 - mu, c1 = v1 - mu, c2 = v2 - mu;
    float ss = blockReduceSum(c0*c0 + c1*c1 + c2*c2, sh);
    float inv = rsqrtf(ss * (1.0f / 768.0f) + 1e-5f);
    float* yr = Y + base;
    yr[i0] = c0 * inv * w[i0] + b[i0];
    yr[i1] = c1 * inv * w[i1] + b[i1];
    yr[i2] = c2 * inv * w[i2] + b[i2];
}

// ------- fused [split-K reduce +] LN + token-shift mix -> fp16 -------------
// RED: 0 = none; 1 = x += q0+q1+q2; 2 = x += gate*(q0+q1+q2)
template<int NMIX, int RED>
__global__ void lnmix_kernel(const float* __restrict__ X,
                             const float* __restrict__ gate,
                             const float* __restrict__ q0,
                             const float* __restrict__ q1,
                             const float* __restrict__ q2,
                             float* __restrict__ Xout,
                             const float* __restrict__ w,
                             const float* __restrict__ b,
                             const float* __restrict__ mk,
                             const float* __restrict__ mv,
                             const float* __restrict__ mr,
                             __half* __restrict__ oh) {
    __shared__ float2 sh[8];
    int m = blockIdx.x;
    bool hasPrev = (m & (Tt - 1)) != 0;
    size_t bc = (size_t)m * Dd;
    size_t bp = bc - Dd;

    float cur[3], prv[3];
    #pragma unroll
    for (int q = 0; q < 3; q++) {
        int i = threadIdx.x + q * 256;
        float v = X[bc + i];
        if (RED == 1) v += q0[bc+i] + q1[bc+i] + q2[bc+i];
        else if (RED == 2) v += gate[bc+i] * (q0[bc+i] + q1[bc+i] + q2[bc+i]);
        if (RED) Xout[bc + i] = v;
        cur[q] = v;
        float p = 0.0f;
        if (hasPrev) {
            p = X[bp + i];
            if (RED == 1) p += q0[bp+i] + q1[bp+i] + q2[bp+i];
            else if (RED == 2) p += gate[bp+i] * (q0[bp+i] + q1[bp+i] + q2[bp+i]);
        }
        prv[q] = p;
    }

    float2 s = blockReduceSum2(make_float2(cur[0]+cur[1]+cur[2], prv[0]+prv[1]+prv[2]), sh);
    float muc = s.x * (1.0f / 768.0f), mup = s.y * (1.0f / 768.0f);
    float cc[3], pc[3];
    #pragma unroll
    for (int q = 0; q < 3; q++) { cc[q] = cur[q] - muc; pc[q] = prv[q] - mup; }
    float2 ss = blockReduceSum2(make_float2(cc[0]*cc[0]+cc[1]*cc[1]+cc[2]*cc[2],
                                            pc[0]*pc[0]+pc[1]*pc[1]+pc[2]*pc[2]), sh);
    float invc = rsqrtf(ss.x * (1.0f / 768.0f) + 1e-5f);
    float invp = rsqrtf(ss.y * (1.0f / 768.0f) + 1e-5f);

    #pragma unroll
    for (int q = 0; q < 3; q++) {
        int i = threadIdx.x + q * 256;
        float cv = cc[q] * invc * w[i] + b[i];
        float pv = hasPrev ? (pc[q] * invp * w[i] + b[i]) : 0.0f;
        float a = mk[i];
        oh[bc + i] = __float2half(cv * a + pv * (1.0f - a));
        if (NMIX == 3) {
            float c = mv[i];
            oh[MD + bc + i] = __float2half(cv * c + pv * (1.0f - c));
        }
        float e = mr[i];
        int slot = (NMIX == 3) ? 2 : 1;
        oh[slot * MD + bc + i] = __float2half(cv * e + pv * (1.0f - e));
    }
}

// ---------------- WKV sequential recurrence (per-channel) ----------------
__global__ void wkv_kernel(const float* __restrict__ k,
                           const float* __restrict__ v,
                           const float* __restrict__ r,
                           const float* __restrict__ tf,
                           const float* __restrict__ td,
                           __half* __restrict__ oh) {
    int ch = blockIdx.x * 32 + threadIdx.x;
    int b = ch / Dd, d = ch % Dd;
    float tfd = tf[d], tdd = td[d];
    float aa = 0.0f, bb = 0.0f, pp = -1e30f;
    size_t base = (size_t)b * Tt * Dd + d;
    float kb[2], vb[2], rb[2];
    kb[0] = k[base];        vb[0] = v[base];        rb[0] = r[base];
    kb[1] = k[base + Dd];   vb[1] = v[base + Dd];   rb[1] = r[base + Dd];
    for (int t = 0; t < Tt; t++) {
        float kc = kb[t & 1], vc = vb[t & 1], rc = rb[t & 1];
        if (t + 2 < Tt) {
            size_t nb = base + (size_t)(t + 2) * Dd;
            kb[t & 1] = k[nb]; vb[t & 1] = v[nb]; rb[t & 1] = r[nb];
        }
        float ww = tfd + kc;
        float p  = fmaxf(pp, ww);
        float e1 = __expf(pp - p);
        float e2 = __expf(ww - p);
        float wkv = __fdividef(e1 * aa + e2 * vc, e1 * bb + e2);
        float sr = __fdividef(1.0f, 1.0f + __expf(-rc));
        oh[base + (size_t)t * Dd] = __float2half(sr * wkv);
        float ww2 = pp + tdd;
        float p2  = fmaxf(ww2, kc);
        float e1b = __expf(ww2 - p2);
        float e2b = __expf(kc - p2);
        aa = e1b * aa + e2b * vc;
        bb = e1b * bb + e2b;
        pp = p2;
    }
}

// ---------------- tensor-core GEMM: fp16 x fp16[K,N], fp32 acc -------------
// A: [M,lda] fp16 row-major. W: [K,ldb] fp16 row-major (N contiguous).
// BM=64, BN=128, BK=32; 256 threads = 8 warps (2m x 4n), warp tile 32x32.
// (Exact R11 configuration — best measured.)
// epi: 0 = store fp32; 2 = sqrelu -> fp16 (staged); 3 = sigmoid -> fp32
struct GArg {
    const __half *A, *W;
    float* C;
    __half* C2;
    int Ng, Kg, kOff, lda, ldb, epi;
};
struct GPack { GArg g[4]; };

#define BM 64
#define BN 128
#define BK 32
#define AST 40    // A row stride (halves)
#define BST 136   // B row stride (halves)

struct Stage {
    __half Ah[BM][AST];   // 5120 B
    __half Bw[BK][BST];   // 8704 B
};
#define GSMEM 41472

__global__ __launch_bounds__(256, 3)
void gemm_h(GPack pk) {
    GArg ga = pk.g[blockIdx.z];
    const int n0 = blockIdx.x * BN;
    if (n0 >= ga.Ng) return;

    extern __shared__ __align__(16) char smraw[];
    Stage* st = reinterpret_cast<Stage*>(smraw);
    float (*Csm)[BN + 4] = reinterpret_cast<float(*)[BN + 4]>(smraw);

    const int tid = threadIdx.x;
    const int wid = tid >> 5;
    const int wm = wid & 1;        // 0..1 -> 32 rows each
    const int wn = wid >> 1;       // 0..3 -> 32 cols each
    const int m0 = blockIdx.y * BM;

    const int ar = tid >> 2;           // 0..63
    const int ac = (tid & 3) * 8;      // 0,8,16,24
    const int br = tid >> 3;           // 0..31
    const int bc = (tid & 7) * 16;     // 0..112

    const __half* pA = ga.A + (size_t)(m0 + ar) * ga.lda + ga.kOff + ac;
    const __half* pW = ga.W + (size_t)(ga.kOff + br) * ga.ldb + n0 + bc;
    const size_t wstep = (size_t)ga.ldb;

    wmma::fragment<wmma::accumulator, 16, 16, 16, float> acc[2][2];
    #pragma unroll
    for (int i = 0; i < 2; i++)
        #pragma unroll
        for (int j = 0; j < 2; j++)
            wmma::fill_fragment(acc[i][j], 0.0f);

    const int nk = ga.Kg / BK;

    auto issue = [&](int s, int c) {
        int k0 = c * BK;
        cpa16(&st[s].Ah[ar][ac], pA + k0);
        cpa16(&st[s].Bw[br][bc],     pW + (size_t)k0 * wstep);
        cpa16(&st[s].Bw[br][bc + 8], pW + (size_t)k0 * wstep + 8);
        cp_commit();
    };

    issue(0, 0);
    if (nk > 1) issue(1, 1);

    for (int c = 0; c < nk; c++) {
        if (c + 1 < nk) cp_wait<1>(); else cp_wait<0>();
        __syncthreads();
        if (c + 2 < nk) issue((c + 2) % 3, c + 2);

        Stage& S = st[c % 3];
        #pragma unroll
        for (int kk = 0; kk < BK; kk += 16) {
            wmma::fragment<wmma::matrix_b, 16, 16, 16, __half, wmma::row_major> bf[2];
            #pragma unroll
            for (int j = 0; j < 2; j++)
                wmma::load_matrix_sync(bf[j], &S.Bw[kk][wn * 32 + j * 16], BST);

            wmma::fragment<wmma::matrix_a, 16, 16, 16, __half, wmma::row_major> af[2];
            #pragma unroll
            for (int i = 0; i < 2; i++)
                wmma::load_matrix_sync(af[i], &S.Ah[wm * 32 + i * 16][kk], AST);
            #pragma unroll
            for (int i = 0; i < 2; i++)
                #pragma unroll
                for (int j = 0; j < 2; j++)
                    wmma::mma_sync(acc[i][j], af[i], bf[j], acc[i][j]);
        }
    }

    const int Ng = ga.Ng, epi = ga.epi;

    if (epi == 2) {
        __syncthreads();
        #pragma unroll
        for (int i = 0; i < 2; i++)
            #pragma unroll
            for (int j = 0; j < 2; j++)
                wmma::store_matrix_sync(&Csm[wm * 32 + i * 16][wn * 32 + j * 16],
                                        acc[i][j], BN + 4, wmma::mem_row_major);
        __syncthreads();
        const int ecol = tid & 127;
        const int erow = tid >> 7;
        #pragma unroll
        for (int i = 0; i < 32; i++) {
            int rr = i * 2 + erow;
            size_t idx = (size_t)(m0 + rr) * Ng + n0 + ecol;
            float t0 = fmaxf(Csm[rr][ecol], 0.0f);
            ga.C2[idx] = __float2half(t0 * t0);
        }
    } else {
        if (epi == 3) {
            #pragma unroll
            for (int i = 0; i < 2; i++)
                #pragma unroll
                for (int j = 0; j < 2; j++)
                    #pragma unroll
                    for (int e = 0; e < acc[i][j].num_elements; e++)
                        acc[i][j].x[e] = __fdividef(1.0f, 1.0f + __expf(-acc[i][j].x[e]));
        }
        #pragma unroll
        for (int i = 0; i < 2; i++)
            #pragma unroll
            for (int j = 0; j < 2; j++)
                wmma::store_matrix_sync(
                    ga.C + (size_t)(m0 + wm * 32 + i * 16) * Ng + n0 + wn * 32 + j * 16,
                    acc[i][j], Ng, wmma::mem_row_major);
    }
}

// ---------------- host launcher ----------------
extern "C" void kernel_launch(void* const* d_in, const int* in_sizes, int n_in,
                              void* d_out, int out_size) {
    const int*   tokens     = (const int*)  d_in[0];
    const float* emb        = (const float*)d_in[1];
    const float* ln0_w      = (const float*)d_in[2];
    const float* ln0_b      = (const float*)d_in[3];
    const float* ln1_w      = (const float*)d_in[4];
    const float* ln1_b      = (const float*)d_in[5];
    const float* ln2_w      = (const float*)d_in[6];
    const float* ln2_b      = (const float*)d_in[7];
    const float* att_mix_k  = (const float*)d_in[8];
    const float* att_mix_v  = (const float*)d_in[9];
    const float* att_mix_r  = (const float*)d_in[10];
    const float* time_first = (const float*)d_in[11];
    const float* time_decay = (const float*)d_in[12];
    const float* att_Wk     = (const float*)d_in[13];
    const float* att_Wv     = (const float*)d_in[14];
    const float* att_Wr     = (const float*)d_in[15];
    const float* att_Wo     = (const float*)d_in[16];
    const float* ffn_mix_k  = (const float*)d_in[17];
    const float* ffn_mix_r  = (const float*)d_in[18];
    const float* ffn_Wk     = (const float*)d_in[19];
    const float* ffn_Wv     = (const float*)d_in[20];
    const float* ffn_Wr     = (const float*)d_in[21];
    const float* lnout_w    = (const float*)d_in[22];
    const float* lnout_b    = (const float*)d_in[23];
    float* out = (float*)d_out;

    float *xa, *xb, *kvr, *r2, *part;
    __half *mixh, *rwkvh, *hh, *w16;
    cudaGetSymbolAddress((void**)&xa,    g_x);
    cudaGetSymbolAddress((void**)&xb,    g_x2);
    cudaGetSymbolAddress((void**)&kvr,   g_kvr);
    cudaGetSymbolAddress((void**)&r2,    g_r2);
    cudaGetSymbolAddress((void**)&part,  g_part);
    cudaGetSymbolAddress((void**)&mixh,  g_mixh);
    cudaGetSymbolAddress((void**)&rwkvh, g_rwkvh);
    cudaGetSymbolAddress((void**)&hh,    g_hh);
    cudaGetSymbolAddress((void**)&w16,   g_w);

    cudaFuncSetAttribute(gemm_h, cudaFuncAttributeMaxDynamicSharedMemorySize, GSMEM);

    // ---- one fused conversion launch for all 7 weights ----
    {
        ConvArgs ca{};
        const float* srcs[7] = {att_Wk, att_Wv, att_Wr, att_Wo, ffn_Wk, ffn_Wv, ffn_Wr};
        size_t offs[7] = {OFF_WK, OFF_WV, OFF_WR, OFF_WO, OFF_FK, OFF_FV, OFF_FR};
        int ns[7] = {NDD, NDD, NDD, NDD, NDF, NDF, NDD};
        int cum = 0;
        for (int t = 0; t < 7; t++) {
            ca.src[t] = (const float4*)srcs[t];
            ca.dst[t] = (uint4*)(w16 + offs[t]);
            ca.n8[t] = ns[t] / 8;
            ca.cum[t] = cum;
            cum += (ca.n8[t] + 1023) / 1024;
        }
        ca.cum[7] = cum;
        convAll_kernel<<<cum, 256>>>(ca);
    }

    // x(a) = LN0(emb[tokens])
    embed_ln_kernel<<<MM, 256>>>(tokens, emb, ln0_w, ln0_b, xa);

    for (int l = 0; l < Ll; l++) {
        // ---- time mixing: [gated FV reduce +] LN1 + mix3 ----
        if (l == 0) {
            lnmix_kernel<3, 0><<<MM, 256>>>(xa, nullptr, nullptr, nullptr, nullptr, nullptr,
                                            ln1_w, ln1_b,
                                            att_mix_k, att_mix_v, att_mix_r, mixh);
        } else {
            lnmix_kernel<3, 2><<<MM, 256>>>(xb, r2, part, part + MD, part + 2 * MD, xa,
                                            ln1_w + l * Dd, ln1_b + l * Dd,
                                            att_mix_k + l * Dd, att_mix_v + l * Dd,
                                            att_mix_r + l * Dd, mixh);
        }
        // k/v/r = mix @ {Wk,Wv,Wr}
        {
            GPack pk{};
            for (int z = 0; z < 3; z++) {
                pk.g[z].A = mixh + z * MD;
                size_t wo = (z == 0 ? OFF_WK : z == 1 ? OFF_WV : OFF_WR) + (size_t)l * Dd * Dd;
                pk.g[z].W = w16 + wo;
                pk.g[z].C = kvr + z * MD;
                pk.g[z].Ng = Dd; pk.g[z].Kg = Dd; pk.g[z].kOff = 0;
                pk.g[z].lda = Dd; pk.g[z].ldb = Dd; pk.g[z].epi = 0;
            }
            gemm_h<<<dim3(Dd / BN, MM / BM, 3), 256, GSMEM>>>(pk);
        }
        // sequential WKV (sigmoid inside), 1 channel/thread, prefetch d=2
        wkv_kernel<<<(Bb * Dd) / 32, 32>>>(kvr, kvr + MD, kvr + 2 * MD,
                                           time_first + l * Dd, time_decay + l * Dd, rwkvh);
        // Wo GEMM, split-K=3 -> partials
        {
            GPack pk{};
            for (int z = 0; z < 3; z++) {
                pk.g[z].A = rwkvh;
                pk.g[z].W = w16 + OFF_WO + (size_t)l * Dd * Dd;
                pk.g[z].C = part + z * MD;
                pk.g[z].Ng = Dd; pk.g[z].Kg = Dd / 3; pk.g[z].kOff = z * (Dd / 3);
                pk.g[z].lda = Dd; pk.g[z].ldb = Dd; pk.g[z].epi = 0;
            }
            gemm_h<<<dim3(Dd / BN, MM / BM, 3), 256, GSMEM>>>(pk);
        }
        // ---- channel mixing: Wo reduce + LN2 + mix2 (xa + parts -> xb) ----
        lnmix_kernel<2, 1><<<MM, 256>>>(xa, nullptr, part, part + MD, part + 2 * MD, xb,
                                        ln2_w + l * Dd, ln2_b + l * Dd,
                                        ffn_mix_k + l * Dd, nullptr, ffn_mix_r + l * Dd, mixh);
        // FK: h = sqrelu(xk2 @ ffn_Wk) -> fp16
        {
            GPack pk{};
            pk.g[0].A = mixh;
            pk.g[0].W = w16 + OFF_FK + (size_t)l * Dd * Ff;
            pk.g[0].C2 = hh;
            pk.g[0].Ng = Ff; pk.g[0].Kg = Dd; pk.g[0].kOff = 0;
            pk.g[0].lda = Dd; pk.g[0].ldb = Ff; pk.g[0].epi = 2;
            gemm_h<<<dim3(Ff / BN, MM / BM, 1), 256, GSMEM>>>(pk);
        }
        // FV split-K=3 (z=0..2) batched with FR sigmoid (z=3)
        {
            GPack pk{};
            for (int z = 0; z < 3; z++) {
                pk.g[z].A = hh;
                pk.g[z].W = w16 + OFF_FV + (size_t)l * Ff * Dd;
                pk.g[z].C = part + z * MD;
                pk.g[z].Ng = Dd; pk.g[z].Kg = Ff / 3; pk.g[z].kOff = z * (Ff / 3);
                pk.g[z].lda = Ff; pk.g[z].ldb = Dd; pk.g[z].epi = 0;
            }
            pk.g[3].A = mixh + MD;
            pk.g[3].W = w16 + OFF_FR + (size_t)l * Dd * Dd;
            pk.g[3].C = r2;
            pk.g[3].Ng = Dd; pk.g[3].Kg = Dd; pk.g[3].kOff = 0;
            pk.g[3].lda = Dd; pk.g[3].ldb = Dd; pk.g[3].epi = 3;
            gemm_h<<<dim3(Dd / BN, MM / BM, 4), 256, GSMEM>>>(pk);
        }
    }

    // out = LN_out(xb + r2*(parts))
    ln_red_kernel<<<MM, 256>>>(xb, r2, part, part + MD, part + 2 * MD,
                               lnout_w, lnout_b, out);
}